// round 1
// baseline (speedup 1.0000x reference)
#include <cuda_runtime.h>
#include <cuda_bf16.h>
#include <cstdint>

// Problem shape (fixed for this problem id)
#define BB   16
#define SS   768
#define DE   16
#define HID  128
#define BSN  (BB*SS)          // 12288 rows
#define ROWF (SS*DE)          // 12288 floats per (b,i) row
#define ROWF4 (ROWF/4)        // 3072 float4 per row

// ---- scratch (no allocations allowed) ----
__device__ float g_edge_sum[BSN];
__device__ float g_dist[BSN];
__device__ float g_imp[BSN];
__device__ float g_wnc[HID];
__device__ float g_v[64];
__device__ float g_C[1];
__device__ unsigned char g_mask[BSN];

// ============================================================================
// Kernel 1: prep — detect pocket_mask dtype, canonicalize, fold weights.
//   w_nc = W_node @ W_imp[:32]          (128)
//   v    = W_e2  @ W_imp[32:]           (64)
//   C    = b_node.W_imp[:32] + b_e2.W_imp[32:] + b_imp
// ============================================================================
__global__ void prep_kernel(const void* __restrict__ pocket_raw,
                            const float* __restrict__ W_node,
                            const float* __restrict__ b_node,
                            const float* __restrict__ W_e2,
                            const float* __restrict__ b_e2,
                            const float* __restrict__ W_imp,
                            const float* __restrict__ b_imp)
{
    __shared__ int s_fone, s_other;
    const int t = threadIdx.x;
    if (t == 0) { s_fone = 0; s_other = 0; }
    __syncthreads();

    // Scan only the first BSN bytes (= BSN/4 words) — safe for bool/int/float.
    const unsigned int* w = (const unsigned int*)pocket_raw;
    int lf = 0, lo = 0;
    for (int k = t; k < BSN / 4; k += 256) {
        unsigned int x = w[k];
        if (x == 0x3F800000u) lf++;
        else if (x != 0u && x != 1u) lo++;
    }
    if (lf) atomicAdd(&s_fone, lf);
    if (lo) atomicAdd(&s_other, lo);
    __syncthreads();
    // mode: 0=float32 (saw 1.0f words), 2=bool/u8 (saw packed-byte patterns), 1=int32
    const int mode = (s_fone > 0) ? 0 : ((s_other > 0) ? 2 : 1);

    for (int idx = t; idx < BSN; idx += 256) {
        bool m;
        if (mode == 0)      m = ((const float*)pocket_raw)[idx] != 0.0f;
        else if (mode == 1) m = ((const int*)pocket_raw)[idx] != 0;
        else                m = ((const unsigned char*)pocket_raw)[idx] != 0;
        g_mask[idx] = m ? 1 : 0;
    }

    if (t < HID) {
        float s = 0.0f;
        #pragma unroll
        for (int k = 0; k < 32; k++) s += W_node[t * 32 + k] * W_imp[k];
        g_wnc[t] = s;
    }
    if (t < 64) {
        float s = 0.0f;
        #pragma unroll
        for (int k = 0; k < 32; k++) s += W_e2[t * 32 + k] * W_imp[32 + k];
        g_v[t] = s;
    }
    if (t == 0) {
        float c = b_imp[0];
        #pragma unroll
        for (int k = 0; k < 32; k++) c += b_node[k] * W_imp[k];
        #pragma unroll
        for (int k = 0; k < 32; k++) c += b_e2[k] * W_imp[32 + k];
        g_C[0] = c;
    }
}

// ============================================================================
// Kernel 2: edge pass — the 604 MB streaming pass.
// One block per (b,i) row: fused (sum over S*De) + (masked min over channel 0).
// float4 loads; channel-0 element sits at float index j*16 -> float4 index k
// with k%4==0, component .x, j = k>>2.
// ============================================================================
__global__ void __launch_bounds__(256) edge_kernel(const float* __restrict__ edge)
{
    const int i = blockIdx.x;
    const int b = blockIdx.y;
    const int t = threadIdx.x;

    __shared__ unsigned char sm[SS];
    for (int k = t; k < SS; k += 256) sm[k] = g_mask[b * SS + k];
    __syncthreads();

    const float4* __restrict__ row =
        (const float4*)(edge + ((size_t)(b * SS + i)) * (size_t)ROWF);

    float sum = 0.0f;
    float mn  = __int_as_float(0x7f800000);  // +inf
    #pragma unroll
    for (int it = 0; it < ROWF4 / 256; it++) {
        const int k = t + it * 256;
        float4 v = __ldg(row + k);
        sum += (v.x + v.y) + (v.z + v.w);
        if ((k & 3) == 0) {                 // channel 0 of edge feature j
            const int j = k >> 2;
            if (sm[j]) mn = fminf(mn, v.x);
        }
    }

    // warp reduce
    #pragma unroll
    for (int o = 16; o; o >>= 1) {
        sum += __shfl_xor_sync(0xFFFFFFFFu, sum, o);
        mn   = fminf(mn, __shfl_xor_sync(0xFFFFFFFFu, mn, o));
    }
    __shared__ float ssum[8], smn[8];
    const int wid = t >> 5, lid = t & 31;
    if (lid == 0) { ssum[wid] = sum; smn[wid] = mn; }
    __syncthreads();
    if (t == 0) {
        float S = 0.0f, M = __int_as_float(0x7f800000);
        #pragma unroll
        for (int k = 0; k < 8; k++) { S += ssum[k]; M = fminf(M, smn[k]); }
        g_edge_sum[b * SS + i] = S;
        g_dist[b * SS + i]     = M;
    }
}

// ============================================================================
// Kernel 3: importance — one warp per row.
//   logit = node_row . w_nc  +  sum_j relu(es*We1[j]+be1[j]) * v[j]  +  C
//   imp   = sigmoid(logit) * sequence_mask
// ============================================================================
__global__ void __launch_bounds__(256) imp_kernel(const float* __restrict__ node,
                                                  const float* __restrict__ seqmask,
                                                  const float* __restrict__ We1,
                                                  const float* __restrict__ be1)
{
    __shared__ float swnc[HID], sv[64], sw1[64], sb1[64];
    const int t = threadIdx.x;
    if (t < HID) swnc[t] = g_wnc[t];
    if (t < 64) { sv[t] = g_v[t]; sw1[t] = We1[t]; sb1[t] = be1[t]; }
    __syncthreads();

    const int w = t >> 5, l = t & 31;
    const int row = blockIdx.x * 8 + w;   // BSN/8 blocks

    const float4* nr = (const float4*)(node + (size_t)row * HID);
    const float4 nv = __ldg(nr + l);      // 32 lanes x float4 = 128 elems
    float acc = nv.x * swnc[l * 4 + 0] + nv.y * swnc[l * 4 + 1]
              + nv.z * swnc[l * 4 + 2] + nv.w * swnc[l * 4 + 3];

    const float es = g_edge_sum[row] * (1.0f / (float)ROWF);
    const float h0 = fmaxf(es * sw1[l]      + sb1[l],      0.0f);
    const float h1 = fmaxf(es * sw1[l + 32] + sb1[l + 32], 0.0f);
    acc += h0 * sv[l] + h1 * sv[l + 32];

    #pragma unroll
    for (int o = 16; o; o >>= 1) acc += __shfl_xor_sync(0xFFFFFFFFu, acc, o);

    if (l == 0) {
        const float logit = acc + g_C[0];
        const float imp = 1.0f / (1.0f + expf(-logit));   // accurate exp
        g_imp[row] = imp * seqmask[row];
    }
}

// ============================================================================
// Kernel 4: finalize — one block per batch.
//   imp_mean (== imp_full); merged = pocket|core|shell; select branch.
// ============================================================================
__global__ void __launch_bounds__(256) final_kernel(float* __restrict__ out, int out_size)
{
    const int b = blockIdx.x, t = threadIdx.x;
    __shared__ float red[256];
    __shared__ float s_mean;

    float s = 0.0f;
    for (int k = t; k < SS; k += 256) s += g_imp[b * SS + k];
    red[t] = s; __syncthreads();
    #pragma unroll
    for (int o = 128; o; o >>= 1) { if (t < o) red[t] += red[t + o]; __syncthreads(); }
    if (t == 0) s_mean = red[0] * (1.0f / (float)SS);
    __syncthreads();
    const float mean = s_mean;

    int cnt = 0, anyp = 0;
    for (int k = t; k < SS; k += 256) {
        const int idx = b * SS + k;
        const bool p = g_mask[idx] != 0;
        const float d = g_dist[idx];
        const bool core  = d < 6.0f;
        const bool shell = (d >= 6.0f) && (d < 10.0f) && (g_imp[idx] > mean);
        if (p | core | shell) cnt++;
        if (p) anyp = 1;
    }
    __shared__ int ic[256], ip[256];
    ic[t] = cnt; ip[t] = anyp; __syncthreads();
    #pragma unroll
    for (int o = 128; o; o >>= 1) {
        if (t < o) { ic[t] += ic[t + o]; ip[t] |= ip[t + o]; }
        __syncthreads();
    }

    if (t == 0) {
        float chunk;
        if (ip[0]) {
            int ml = ic[0]; if (ml > 256) ml = 256;            // merged_len clamp
            chunk = fminf(fmaxf((float)ml, 64.0f), 256.0f);    // clamp(adj=64, 256)
        } else {
            chunk = fminf(fmaxf(64.0f * mean, 32.0f), 128.0f); // clip(64*imp, 32, 128)
        }
        out[b] = chunk;
        if (b == 0) {
            for (int k = BB; k < out_size; k++) out[k] = 256.0f;  // MAX_SEQ_LEN
        }
    }
}

// ============================================================================
extern "C" void kernel_launch(void* const* d_in, const int* in_sizes, int n_in,
                              void* d_out, int out_size)
{
    const float* node    = (const float*)d_in[0];   // [16,768,128]
    const float* edge    = (const float*)d_in[1];   // [16,768,768,16]
    const float* seqmask = (const float*)d_in[2];   // [16,768]
    const void*  pocket  = d_in[3];                 // [16,768] dtype detected at runtime
    const float* W_node  = (const float*)d_in[4];
    const float* b_node  = (const float*)d_in[5];
    const float* W_e1    = (const float*)d_in[6];
    const float* b_e1    = (const float*)d_in[7];
    const float* W_e2    = (const float*)d_in[8];
    const float* b_e2    = (const float*)d_in[9];
    const float* W_imp   = (const float*)d_in[10];
    const float* b_imp   = (const float*)d_in[11];
    float* out = (float*)d_out;

    prep_kernel<<<1, 256>>>(pocket, W_node, b_node, W_e2, b_e2, W_imp, b_imp);

    dim3 eg(SS, BB);
    edge_kernel<<<eg, 256>>>(edge);

    imp_kernel<<<BSN / 8, 256>>>(node, seqmask, W_e1, b_e1);

    final_kernel<<<BB, 256>>>(out, out_size);
}

// round 2
// speedup vs baseline: 1.1148x; 1.1148x over previous
#include <cuda_runtime.h>
#include <cuda_bf16.h>
#include <cstdint>

// Problem shape (fixed for this problem id)
#define BB   16
#define SS   768
#define DE   16
#define HID  128
#define BSN  (BB*SS)          // 12288 rows
#define ROWF (SS*DE)          // 12288 floats per (b,i) row
#define ROWF4 (ROWF/4)        // 3072 float4 per row

// ---- scratch (no allocations allowed) ----
__device__ float g_edge_sum[BSN];
__device__ float g_dist[BSN];
__device__ float g_imp[BSN];
__device__ float g_wnc[HID];
__device__ float g_v[64];
__device__ float g_C[1];
__device__ unsigned char g_mask[BSN];

// ============================================================================
// Kernel 1: prep — detect pocket_mask dtype, canonicalize, fold weights.
//   w_nc = W_node @ W_imp[:32]          (128)
//   v    = W_e2  @ W_imp[32:]           (64)
//   C    = b_node.W_imp[:32] + b_e2.W_imp[32:] + b_imp
// ============================================================================
__global__ void prep_kernel(const void* __restrict__ pocket_raw,
                            const float* __restrict__ W_node,
                            const float* __restrict__ b_node,
                            const float* __restrict__ W_e2,
                            const float* __restrict__ b_e2,
                            const float* __restrict__ W_imp,
                            const float* __restrict__ b_imp)
{
    __shared__ int s_fone, s_other;
    const int t = threadIdx.x;
    if (t == 0) { s_fone = 0; s_other = 0; }
    __syncthreads();

    // Scan only the first BSN bytes (= BSN/4 words) — safe for bool/int/float.
    const unsigned int* w = (const unsigned int*)pocket_raw;
    int lf = 0, lo = 0;
    for (int k = t; k < BSN / 4; k += 256) {
        unsigned int x = w[k];
        if (x == 0x3F800000u) lf++;
        else if (x != 0u && x != 1u) lo++;
    }
    if (lf) atomicAdd(&s_fone, lf);
    if (lo) atomicAdd(&s_other, lo);
    __syncthreads();
    // mode: 0=float32 (saw 1.0f words), 2=bool/u8 (saw packed-byte patterns), 1=int32
    const int mode = (s_fone > 0) ? 0 : ((s_other > 0) ? 2 : 1);

    for (int idx = t; idx < BSN; idx += 256) {
        bool m;
        if (mode == 0)      m = ((const float*)pocket_raw)[idx] != 0.0f;
        else if (mode == 1) m = ((const int*)pocket_raw)[idx] != 0;
        else                m = ((const unsigned char*)pocket_raw)[idx] != 0;
        g_mask[idx] = m ? 1 : 0;
    }

    if (t < HID) {
        float s = 0.0f;
        #pragma unroll
        for (int k = 0; k < 32; k++) s += W_node[t * 32 + k] * W_imp[k];
        g_wnc[t] = s;
    }
    if (t < 64) {
        float s = 0.0f;
        #pragma unroll
        for (int k = 0; k < 32; k++) s += W_e2[t * 32 + k] * W_imp[32 + k];
        g_v[t] = s;
    }
    if (t == 0) {
        float c = b_imp[0];
        #pragma unroll
        for (int k = 0; k < 32; k++) c += b_node[k] * W_imp[k];
        #pragma unroll
        for (int k = 0; k < 32; k++) c += b_e2[k] * W_imp[32 + k];
        g_C[0] = c;
    }
}

// ============================================================================
// Kernel 2: edge pass — the 604 MB streaming pass.
// One block per (b,i) row: fused (sum over S*De) + (masked min over channel 0).
// Streaming loads (__ldcs): each byte is touched exactly once.
// Channel-0 element sits at float4 index k with k%4==0, component .x, j=k>>2.
// ============================================================================
__global__ void __launch_bounds__(256) edge_kernel(const float* __restrict__ edge)
{
    const int i = blockIdx.x;
    const int b = blockIdx.y;
    const int t = threadIdx.x;

    __shared__ unsigned char sm[SS];
    for (int k = t; k < SS; k += 256) sm[k] = g_mask[b * SS + k];
    __syncthreads();

    const float4* __restrict__ row =
        (const float4*)(edge + ((size_t)(b * SS + i)) * (size_t)ROWF);

    const float INF = __int_as_float(0x7f800000);
    float sum0 = 0.0f, sum1 = 0.0f;
    float mn = INF;
    #pragma unroll
    for (int it = 0; it < ROWF4 / 256; it++) {
        const int k = t + it * 256;
        float4 v = __ldcs(row + k);
        if (it & 1) sum1 += (v.x + v.y) + (v.z + v.w);
        else        sum0 += (v.x + v.y) + (v.z + v.w);
        if ((k & 3) == 0) {                 // channel 0 of edge feature j
            const int j = k >> 2;
            const float cand = sm[j] ? v.x : INF;   // select, no branch
            mn = fminf(mn, cand);
        }
    }
    float sum = sum0 + sum1;

    // warp reduce
    #pragma unroll
    for (int o = 16; o; o >>= 1) {
        sum += __shfl_xor_sync(0xFFFFFFFFu, sum, o);
        mn   = fminf(mn, __shfl_xor_sync(0xFFFFFFFFu, mn, o));
    }
    __shared__ float ssum[8], smn[8];
    const int wid = t >> 5, lid = t & 31;
    if (lid == 0) { ssum[wid] = sum; smn[wid] = mn; }
    __syncthreads();
    if (t == 0) {
        float S = 0.0f, M = INF;
        #pragma unroll
        for (int k = 0; k < 8; k++) { S += ssum[k]; M = fminf(M, smn[k]); }
        g_edge_sum[b * SS + i] = S;
        g_dist[b * SS + i]     = M;
    }
}

// ============================================================================
// Kernel 3: importance — one warp per row (1536 blocks, full chip).
//   logit = node_row . w_nc  +  sum_j relu(es*We1[j]+be1[j]) * v[j]  +  C
//   imp   = sigmoid(logit) * sequence_mask
// ============================================================================
__global__ void __launch_bounds__(256) imp_kernel(const float* __restrict__ node,
                                                  const float* __restrict__ seqmask,
                                                  const float* __restrict__ We1,
                                                  const float* __restrict__ be1)
{
    __shared__ float swnc[HID], sv[64], sw1[64], sb1[64];
    const int t = threadIdx.x;
    if (t < HID) swnc[t] = g_wnc[t];
    if (t < 64) { sv[t] = g_v[t]; sw1[t] = We1[t]; sb1[t] = be1[t]; }
    __syncthreads();

    const int w = t >> 5, l = t & 31;
    const int row = blockIdx.x * 8 + w;   // BSN/8 blocks

    const float4* nr = (const float4*)(node + (size_t)row * HID);
    const float4 nv = __ldg(nr + l);      // 32 lanes x float4 = 128 elems
    float acc = nv.x * swnc[l * 4 + 0] + nv.y * swnc[l * 4 + 1]
              + nv.z * swnc[l * 4 + 2] + nv.w * swnc[l * 4 + 3];

    const float es = g_edge_sum[row] * (1.0f / (float)ROWF);
    const float h0 = fmaxf(es * sw1[l]      + sb1[l],      0.0f);
    const float h1 = fmaxf(es * sw1[l + 32] + sb1[l + 32], 0.0f);
    acc += h0 * sv[l] + h1 * sv[l + 32];

    #pragma unroll
    for (int o = 16; o; o >>= 1) acc += __shfl_xor_sync(0xFFFFFFFFu, acc, o);

    if (l == 0) {
        const float logit = acc + g_C[0];
        const float imp = 1.0f / (1.0f + expf(-logit));   // accurate exp
        g_imp[row] = imp * seqmask[row];
    }
}

// ============================================================================
// Kernel 4: finalize — one block per batch; shuffle reductions, 3 barriers.
//   imp_mean (== imp_full); merged = pocket|core|shell; select branch.
// ============================================================================
__global__ void __launch_bounds__(256) final_kernel(float* __restrict__ out, int out_size)
{
    const int b = blockIdx.x, t = threadIdx.x;
    const int w = t >> 5, l = t & 31;
    __shared__ float wred[8];
    __shared__ float s_mean;
    __shared__ int   wcnt[8], wany[8];

    // ---- mean of imp over the batch (deterministic fixed order) ----
    float s = 0.0f;
    #pragma unroll
    for (int it = 0; it < SS / 256; it++) s += g_imp[b * SS + t + it * 256];
    #pragma unroll
    for (int o = 16; o; o >>= 1) s += __shfl_xor_sync(0xFFFFFFFFu, s, o);
    if (l == 0) wred[w] = s;
    __syncthreads();
    if (t == 0) {
        float S = 0.0f;
        #pragma unroll
        for (int k = 0; k < 8; k++) S += wred[k];
        s_mean = S * (1.0f / (float)SS);
    }
    __syncthreads();
    const float mean = s_mean;

    // ---- merged count + any(pocket) ----
    int cnt = 0, anyp = 0;
    #pragma unroll
    for (int it = 0; it < SS / 256; it++) {
        const int idx = b * SS + t + it * 256;
        const bool p = g_mask[idx] != 0;
        const float d = g_dist[idx];
        const bool core  = d < 6.0f;
        const bool shell = (d >= 6.0f) && (d < 10.0f) && (g_imp[idx] > mean);
        cnt += (p | core | shell) ? 1 : 0;
        anyp |= p ? 1 : 0;
    }
    #pragma unroll
    for (int o = 16; o; o >>= 1) {
        cnt  += __shfl_xor_sync(0xFFFFFFFFu, cnt, o);
        anyp |= __shfl_xor_sync(0xFFFFFFFFu, anyp, o);
    }
    if (l == 0) { wcnt[w] = cnt; wany[w] = anyp; }
    __syncthreads();

    if (t == 0) {
        int C = 0, A = 0;
        #pragma unroll
        for (int k = 0; k < 8; k++) { C += wcnt[k]; A |= wany[k]; }
        float chunk;
        if (A) {
            int ml = C; if (ml > 256) ml = 256;                // merged_len clamp
            chunk = fminf(fmaxf((float)ml, 64.0f), 256.0f);    // clamp(adj=64, 256)
        } else {
            chunk = fminf(fmaxf(64.0f * mean, 32.0f), 128.0f); // clip(64*imp, 32, 128)
        }
        out[b] = chunk;
    }
    // pad remaining outputs (MAX_SEQ_LEN) in parallel from block 0
    if (b == 0) {
        for (int k = BB + t; k < out_size; k += 256) out[k] = 256.0f;
    }
}

// ============================================================================
extern "C" void kernel_launch(void* const* d_in, const int* in_sizes, int n_in,
                              void* d_out, int out_size)
{
    const float* node    = (const float*)d_in[0];   // [16,768,128]
    const float* edge    = (const float*)d_in[1];   // [16,768,768,16]
    const float* seqmask = (const float*)d_in[2];   // [16,768]
    const void*  pocket  = d_in[3];                 // [16,768] dtype detected at runtime
    const float* W_node  = (const float*)d_in[4];
    const float* b_node  = (const float*)d_in[5];
    const float* W_e1    = (const float*)d_in[6];
    const float* b_e1    = (const float*)d_in[7];
    const float* W_e2    = (const float*)d_in[8];
    const float* b_e2    = (const float*)d_in[9];
    const float* W_imp   = (const float*)d_in[10];
    const float* b_imp   = (const float*)d_in[11];
    float* out = (float*)d_out;

    prep_kernel<<<1, 256>>>(pocket, W_node, b_node, W_e2, b_e2, W_imp, b_imp);

    dim3 eg(SS, BB);
    edge_kernel<<<eg, 256>>>(edge);

    imp_kernel<<<BSN / 8, 256>>>(node, seqmask, W_e1, b_e1);

    final_kernel<<<BB, 256>>>(out, out_size);
}